// round 13
// baseline (speedup 1.0000x reference)
#include <cuda_runtime.h>
#include <cuda_bf16.h>
#include <math_constants.h>
#include <cstdint>

// Problem constants (fixed by the dataset)
#define B_  4
#define S_  1024
#define E_  1024
#define H_  16
#define D_  64
#define M_  (B_ * S_)

// Scratch: Q/K tf32-pre-rounded fp32 [bh][s][d]; V bf16 hi/lo transposed [bh][d][s].
__device__ float g_q[B_*H_*S_*D_], g_k[B_*H_*S_*D_];
__device__ __nv_bfloat16 g_vth[B_*H_*S_*D_], g_vtl[B_*H_*S_*D_];

// ---------------------------------------------------------------------------
// Helpers
// ---------------------------------------------------------------------------
__device__ __forceinline__ void mma16816(float* d, const uint32_t* a, const uint32_t* b) {
    asm volatile(
        "mma.sync.aligned.m16n8k16.row.col.f32.bf16.bf16.f32 "
        "{%0,%1,%2,%3}, {%4,%5,%6,%7}, {%8,%9}, {%0,%1,%2,%3};\n"
        : "+f"(d[0]), "+f"(d[1]), "+f"(d[2]), "+f"(d[3])
        : "r"(a[0]), "r"(a[1]), "r"(a[2]), "r"(a[3]), "r"(b[0]), "r"(b[1]));
}

__device__ __forceinline__ void mma1688_tf32(float* d, const uint32_t* a, const uint32_t* b) {
    asm volatile(
        "mma.sync.aligned.m16n8k8.row.col.f32.tf32.tf32.f32 "
        "{%0,%1,%2,%3}, {%4,%5,%6,%7}, {%8,%9}, {%0,%1,%2,%3};\n"
        : "+f"(d[0]), "+f"(d[1]), "+f"(d[2]), "+f"(d[3])
        : "r"(a[0]), "r"(a[1]), "r"(a[2]), "r"(a[3]), "r"(b[0]), "r"(b[1]));
}

__device__ __forceinline__ uint32_t to_tf32(float f) {
    uint32_t u;
    asm("cvt.rna.tf32.f32 %0, %1;" : "=r"(u) : "f"(f));
    return u;
}

__device__ __forceinline__ float tf32r(float f) {
    return __uint_as_float(to_tf32(f));
}

__device__ __forceinline__ uint32_t pack_bf2(__nv_bfloat16 lo, __nv_bfloat16 hi) {
    uint32_t l = *(const unsigned short*)&lo;
    uint32_t h = *(const unsigned short*)&hi;
    return l | (h << 16);
}

__device__ __forceinline__ void split_bf16(float x, __nv_bfloat16& h, __nv_bfloat16& l) {
    h = __float2bfloat16(x);
    l = __float2bfloat16(x - __bfloat162float(h));
}

__device__ __forceinline__ uint32_t smem_u32(const void* p) {
    return (uint32_t)__cvta_generic_to_shared(p);
}

__device__ __forceinline__ void cp_async16(uint32_t dst, const void* src) {
    asm volatile("cp.async.cg.shared.global [%0], [%1], 16;\n" :: "r"(dst), "l"(src));
}

__device__ __forceinline__ void cp_commit() {
    asm volatile("cp.async.commit_group;" ::: "memory");
}

__device__ __forceinline__ void cp_wait1() {
    asm volatile("cp.async.wait_group 1;" ::: "memory");
}

__device__ __forceinline__ void cp_wait0() {
    asm volatile("cp.async.wait_group 0;" ::: "memory");
}

// ---------------------------------------------------------------------------
// QKV projection GEMM: TF32 single-pass (unchanged from R12 except epilogue).
// ---------------------------------------------------------------------------
#define TBM 128
#define TBN 128
#define TBK 32
#define LDA_W 36
#define LDB_W 136
#define ATW (128 * LDA_W)
#define BTW (TBK * LDB_W)
#define QKV_SMEM (2 * (ATW + BTW) * 4)

__device__ __forceinline__ void qkv_issue(
    float* sm, int st,
    const float* __restrict__ X, const float* __restrict__ W,
    int m0, int n0, int k0, int tid)
{
    float* Abase = sm + st * (ATW + BTW);
    float* Bbase = Abase + ATW;
    #pragma unroll
    for (int u = 0; u < 4; u++) {
        const int idx = tid + u * 256;
        const int row = idx >> 3, seg = idx & 7;
        cp_async16(smem_u32(Abase + row * LDA_W + seg * 4),
                   X + (m0 + row) * E_ + k0 + seg * 4);
    }
    #pragma unroll
    for (int u = 0; u < 4; u++) {
        const int idx = tid + u * 256;
        const int kr = idx >> 5, nq = idx & 31;
        cp_async16(smem_u32(Bbase + kr * LDB_W + nq * 4),
                   W + (k0 + kr) * E_ + n0 + nq * 4);
    }
    cp_commit();
}

__global__ __launch_bounds__(256)
void qkv_mma(const float* __restrict__ X,
             const float* __restrict__ Wq, const float* __restrict__ bq,
             const float* __restrict__ Wk, const float* __restrict__ bk,
             const float* __restrict__ Wv, const float* __restrict__ bv)
{
    extern __shared__ float qsm[];

    const int which = blockIdx.z;
    const float* __restrict__ W    = (which == 0) ? Wq : (which == 1) ? Wk : Wv;
    const float* __restrict__ bias = (which == 0) ? bq : (which == 1) ? bk : bv;

    const int m0 = blockIdx.y * TBM;
    const int n0 = blockIdx.x * TBN;
    const int tid  = threadIdx.x;
    const int warp = tid >> 5;
    const int lane = tid & 31;
    const int wm = (warp >> 2) * 64;
    const int wn = (warp & 3) * 32;

    float acc[4][4][4];
    #pragma unroll
    for (int i = 0; i < 4; i++)
        #pragma unroll
        for (int j = 0; j < 4; j++)
            #pragma unroll
            for (int r = 0; r < 4; r++) acc[i][j][r] = 0.f;

    qkv_issue(qsm, 0, X, W, m0, n0, 0, tid);
    qkv_issue(qsm, 1, X, W, m0, n0, TBK, tid);

    for (int i = 0; i < 32; i++) {
        const int st = i & 1;
        if (i < 30) cp_wait1(); else cp_wait0();
        __syncthreads();

        const float* As = qsm + st * (ATW + BTW);
        const float* Bs = As + ATW;

        #pragma unroll
        for (int ks = 0; ks < TBK; ks += 8) {
            uint32_t a[4][4];
            const int arow = wm + (lane >> 2);
            const int acol = ks + (lane & 3);
            #pragma unroll
            for (int im = 0; im < 4; im++) {
                const int r = arow + im * 16;
                a[im][0] = to_tf32(As[ r      * LDA_W + acol    ]);
                a[im][1] = to_tf32(As[(r + 8) * LDA_W + acol    ]);
                a[im][2] = to_tf32(As[ r      * LDA_W + acol + 4]);
                a[im][3] = to_tf32(As[(r + 8) * LDA_W + acol + 4]);
            }
            uint32_t bfr[4][2];
            const int bk0 = ks + (lane & 3);
            const int bn  = wn + (lane >> 2);
            #pragma unroll
            for (int jn = 0; jn < 4; jn++) {
                const int n = bn + jn * 8;
                bfr[jn][0] = to_tf32(Bs[ bk0      * LDB_W + n]);
                bfr[jn][1] = to_tf32(Bs[(bk0 + 4) * LDB_W + n]);
            }
            #pragma unroll
            for (int im = 0; im < 4; im++)
                #pragma unroll
                for (int jn = 0; jn < 4; jn++)
                    mma1688_tf32(acc[im][jn], a[im], bfr[jn]);
        }
        __syncthreads();
        if (i + 2 < 32)
            qkv_issue(qsm, st, X, W, m0, n0, (i + 2) * TBK, tid);
    }

    // ---- epilogue ----
    if (which < 2) {
        // Q/K: add bias, tf32-round, store fp32 (attention feeds these raw to MMA)
        float* __restrict__ og = (which == 0) ? g_q : g_k;
        #pragma unroll
        for (int jn = 0; jn < 4; jn++) {
            const int ncol = n0 + wn + jn * 8 + ((lane & 3) << 1);
            const int hh = ncol >> 6;
            const int d  = ncol & 63;
            const float b0v = bias[ncol], b1v = bias[ncol + 1];
            #pragma unroll
            for (int im = 0; im < 4; im++) {
                const int row = m0 + wm + im * 16 + (lane >> 2);
                const int bb = row >> 10;
                const int s  = row & (S_ - 1);
                const int base = ((bb * H_ + hh) * S_ + s) * D_ + d;
                float2 v0 = make_float2(tf32r(acc[im][jn][0] + b0v),
                                        tf32r(acc[im][jn][1] + b1v));
                float2 v1 = make_float2(tf32r(acc[im][jn][2] + b0v),
                                        tf32r(acc[im][jn][3] + b1v));
                *(float2*)&og[base] = v0;
                *(float2*)&og[base + 8 * D_] = v1;
            }
        }
    } else {
        // V: split bf16 hi/lo, scatter-transpose to [bh][d][s]
        #pragma unroll
        for (int jn = 0; jn < 4; jn++) {
            const int ncol = n0 + wn + jn * 8 + ((lane & 3) << 1);
            const int hh = ncol >> 6;
            const int d  = ncol & 63;
            const float b0v = bias[ncol], b1v = bias[ncol + 1];
            #pragma unroll
            for (int im = 0; im < 4; im++) {
                const int row = m0 + wm + im * 16 + (lane >> 2);
                const int bb = row >> 10;
                const int s  = row & (S_ - 1);
                const int vb = ((bb * H_ + hh) * D_ + d) * S_ + s;
                __nv_bfloat16 h, l;
                split_bf16(acc[im][jn][0] + b0v, h, l);
                g_vth[vb] = h;            g_vtl[vb] = l;
                split_bf16(acc[im][jn][1] + b1v, h, l);
                g_vth[vb + S_] = h;       g_vtl[vb + S_] = l;
                split_bf16(acc[im][jn][2] + b0v, h, l);
                g_vth[vb + 8] = h;        g_vtl[vb + 8] = l;
                split_bf16(acc[im][jn][3] + b1v, h, l);
                g_vth[vb + S_ + 8] = h;   g_vtl[vb + S_ + 8] = l;
            }
        }
    }
}

// ---------------------------------------------------------------------------
// MMA flash attention: QK^T in TF32 single-pass (Q/K pre-rounded fp32),
// P*V in bf16 3-pass. cp.async 2-stage K/V pipeline. 128 threads, 64 q rows.
// ---------------------------------------------------------------------------
#define QW  68                               // Q/K smem row stride in floats
#define QBYTES (64 * QW * 4)                 // 17408 B per fp32 tile
#define VLD 72                               // V smem row stride in bf16
#define VBYTES (64 * VLD * 2)                // 9216 B per bf16 tile
#define STAGE_B (QBYTES + 2 * VBYTES)        // K + Vh + Vl = 35840 B
#define AT_SMEM_BYTES (QBYTES + 2 * STAGE_B) // Q + 2 stages = 89088 B

__device__ __forceinline__ void attn_issue(
    char* stage_base, int bh, size_t qoff, int t0, int tid)
{
    float* Ks = (float*)stage_base;
    __nv_bfloat16* Vh = (__nv_bfloat16*)(stage_base + QBYTES);
    __nv_bfloat16* Vl = (__nv_bfloat16*)(stage_base + QBYTES + VBYTES);
    // K: 64 rows x 64 floats = 1024 float4
    #pragma unroll
    for (int u = 0; u < 8; u++) {
        const int idx = tid + u * 128;
        const int r = idx >> 4, seg = idx & 15;
        cp_async16(smem_u32(Ks + r * QW + seg * 4),
                   g_k + qoff + (t0 + r) * D_ + seg * 4);
    }
    // V hi/lo: 64 rows x 64 bf16 each = 512 uint4 each
    #pragma unroll
    for (int u = 0; u < 4; u++) {
        const int idx = tid + u * 128;
        const int r = idx >> 3, sg = (idx & 7) * 8;
        cp_async16(smem_u32(Vh + r * VLD + sg),
                   g_vth + (size_t)(bh * D_ + r) * S_ + t0 + sg);
        cp_async16(smem_u32(Vl + r * VLD + sg),
                   g_vtl + (size_t)(bh * D_ + r) * S_ + t0 + sg);
    }
    cp_commit();
}

__global__ __launch_bounds__(128)
void attn_mma(const int* __restrict__ lens, float* __restrict__ out)
{
    extern __shared__ char smem_raw[];
    float* Qs = (float*)smem_raw;
    char* St  = smem_raw + QBYTES;           // stage s at St + s*STAGE_B

    const int bh = blockIdx.y;
    const int b  = bh >> 4;
    const int h  = bh & (H_ - 1);
    const int len = lens[b];
    const int q0 = blockIdx.x * 64;
    const int tid = threadIdx.x;

    // ---- Shortcut: whole block invalid -> uniform mean of V ----
    if (q0 >= len) {
        float* red = (float*)smem_raw;
        const int d = tid & 63;
        const int half = tid >> 6;
        const uint4* ph = (const uint4*)(g_vth + (bh * D_ + d) * S_) + half * 64;
        const uint4* pl = (const uint4*)(g_vtl + (bh * D_ + d) * S_) + half * 64;
        float a = 0.f;
        for (int i = 0; i < 64; i++) {
            uint4 xh = ph[i], xl = pl[i];
            const __nv_bfloat162* eh = (const __nv_bfloat162*)&xh;
            const __nv_bfloat162* el = (const __nv_bfloat162*)&xl;
            #pragma unroll
            for (int e = 0; e < 4; e++) {
                float2 fh = __bfloat1622float2(eh[e]);
                float2 fl = __bfloat1622float2(el[e]);
                a += fh.x + fh.y + fl.x + fl.y;
            }
        }
        red[half * 64 + d] = a;
        __syncthreads();
        const float m = (red[d] + red[64 + d]) * (1.0f / 1024.0f);
        for (int r = half; r < 64; r += 2)
            out[(b * S_ + q0 + r) * E_ + h * D_ + d] = m;
        return;
    }

    const int warp = tid >> 5;
    const int lane = tid & 31;
    const int wm = warp * 16;

    const size_t qoff = (size_t)bh * S_ * D_;

    const bool all_valid = (q0 + 64 <= len);
    const int kend = all_valid ? ((len + 63) & ~63) : S_;
    const int nt = kend >> 6;

    // Start pipeline
    attn_issue(St, bh, qoff, 0, tid);
    if (nt > 1) attn_issue(St + STAGE_B, bh, qoff, 64, tid);

    // Load Q (fp32, 64x64): 1024 float4
    #pragma unroll
    for (int u = 0; u < 8; u++) {
        const int idx = tid + u * 128;
        const int r = idx >> 4, seg = idx & 15;
        *(float4*)&Qs[r * QW + seg * 4] =
            *(const float4*)&g_q[qoff + (q0 + r) * D_ + seg * 4];
    }

    float m0 = -CUDART_INF_F, m1 = -CUDART_INF_F, l0 = 0.f, l1 = 0.f;
    float o[8][4];
    #pragma unroll
    for (int j = 0; j < 8; j++)
        #pragma unroll
        for (int e = 0; e < 4; e++) o[j][e] = 0.f;

    const float scale = 0.125f;
    const int r0g = q0 + wm + (lane >> 2);
    const int r1g = r0g + 8;
    const bool rv0 = r0g < len, rv1 = r1g < len;

    for (int ti = 0; ti < nt; ti++) {
        const int st = ti & 1;
        const int t0 = ti * 64;
        if (ti + 1 < nt) cp_wait1(); else cp_wait0();
        __syncthreads();

        char* stage = St + st * STAGE_B;
        const float* Ks = (const float*)stage;
        const __nv_bfloat16* Vth = (const __nv_bfloat16*)(stage + QBYTES);
        const __nv_bfloat16* Vtl = (const __nv_bfloat16*)(stage + QBYTES + VBYTES);

        // ---- S = Q K^T (tf32 single-pass, k8 steps) ----
        float sc[8][4];
        #pragma unroll
        for (int j = 0; j < 8; j++)
            #pragma unroll
            for (int e = 0; e < 4; e++) sc[j][e] = 0.f;

        #pragma unroll
        for (int kk = 0; kk < 64; kk += 8) {
            uint32_t a[4];
            const int ar = wm + (lane >> 2);
            const int ac = kk + (lane & 3);
            a[0] = *(const uint32_t*)&Qs[ ar      * QW + ac    ];
            a[1] = *(const uint32_t*)&Qs[(ar + 8) * QW + ac    ];
            a[2] = *(const uint32_t*)&Qs[ ar      * QW + ac + 4];
            a[3] = *(const uint32_t*)&Qs[(ar + 8) * QW + ac + 4];
            #pragma unroll
            for (int j = 0; j < 8; j++) {
                const int br = j * 8 + (lane >> 2);
                const int bc = kk + (lane & 3);
                uint32_t bf[2];
                bf[0] = *(const uint32_t*)&Ks[br * QW + bc    ];
                bf[1] = *(const uint32_t*)&Ks[br * QW + bc + 4];
                mma1688_tf32(sc[j], a, bf);
            }
        }

        // ---- mask + scale ----
        #pragma unroll
        for (int j = 0; j < 8; j++) {
            const int c0 = t0 + j * 8 + ((lane & 3) << 1);
            const bool cv0 = c0 < len, cv1 = (c0 + 1) < len;
            sc[j][0] = (rv0 && cv0) ? sc[j][0] * scale : -1e9f;
            sc[j][1] = (rv0 && cv1) ? sc[j][1] * scale : -1e9f;
            sc[j][2] = (rv1 && cv0) ? sc[j][2] * scale : -1e9f;
            sc[j][3] = (rv1 && cv1) ? sc[j][3] * scale : -1e9f;
        }

        // ---- online softmax ----
        float vm0 = -CUDART_INF_F, vm1 = -CUDART_INF_F;
        #pragma unroll
        for (int j = 0; j < 8; j++) {
            vm0 = fmaxf(vm0, fmaxf(sc[j][0], sc[j][1]));
            vm1 = fmaxf(vm1, fmaxf(sc[j][2], sc[j][3]));
        }
        vm0 = fmaxf(vm0, __shfl_xor_sync(0xffffffffu, vm0, 1));
        vm0 = fmaxf(vm0, __shfl_xor_sync(0xffffffffu, vm0, 2));
        vm1 = fmaxf(vm1, __shfl_xor_sync(0xffffffffu, vm1, 1));
        vm1 = fmaxf(vm1, __shfl_xor_sync(0xffffffffu, vm1, 2));
        const float mn0 = fmaxf(m0, vm0);
        const float mn1 = fmaxf(m1, vm1);
        const float al0 = __expf(m0 - mn0);
        const float al1 = __expf(m1 - mn1);
        m0 = mn0; m1 = mn1;

        float s0 = 0.f, s1 = 0.f;
        #pragma unroll
        for (int j = 0; j < 8; j++) {
            sc[j][0] = __expf(sc[j][0] - mn0); s0 += sc[j][0];
            sc[j][1] = __expf(sc[j][1] - mn0); s0 += sc[j][1];
            sc[j][2] = __expf(sc[j][2] - mn1); s1 += sc[j][2];
            sc[j][3] = __expf(sc[j][3] - mn1); s1 += sc[j][3];
        }
        s0 += __shfl_xor_sync(0xffffffffu, s0, 1);
        s0 += __shfl_xor_sync(0xffffffffu, s0, 2);
        s1 += __shfl_xor_sync(0xffffffffu, s1, 1);
        s1 += __shfl_xor_sync(0xffffffffu, s1, 2);
        l0 = l0 * al0 + s0;
        l1 = l1 * al1 + s1;
        #pragma unroll
        for (int j = 0; j < 8; j++) {
            o[j][0] *= al0; o[j][1] *= al0;
            o[j][2] *= al1; o[j][3] *= al1;
        }

        // ---- O += P V (bf16 3-pass) ----
        #pragma unroll
        for (int kp = 0; kp < 4; kp++) {
            const int j0 = kp * 2, j1 = kp * 2 + 1;
            uint32_t pah[4], pal[4];
            {
                __nv_bfloat16 hx, lx, hy, ly;
                split_bf16(sc[j0][0], hx, lx); split_bf16(sc[j0][1], hy, ly);
                pah[0] = pack_bf2(hx, hy); pal[0] = pack_bf2(lx, ly);
                split_bf16(sc[j0][2], hx, lx); split_bf16(sc[j0][3], hy, ly);
                pah[1] = pack_bf2(hx, hy); pal[1] = pack_bf2(lx, ly);
                split_bf16(sc[j1][0], hx, lx); split_bf16(sc[j1][1], hy, ly);
                pah[2] = pack_bf2(hx, hy); pal[2] = pack_bf2(lx, ly);
                split_bf16(sc[j1][2], hx, lx); split_bf16(sc[j1][3], hy, ly);
                pah[3] = pack_bf2(hx, hy); pal[3] = pack_bf2(lx, ly);
            }
            #pragma unroll
            for (int j = 0; j < 8; j++) {
                const int br = j * 8 + (lane >> 2);
                const int bc = kp * 16 + ((lane & 3) << 1);
                uint32_t bhf[2], blf[2];
                bhf[0] = *(const uint32_t*)&Vth[br * VLD + bc    ];
                bhf[1] = *(const uint32_t*)&Vth[br * VLD + bc + 8];
                blf[0] = *(const uint32_t*)&Vtl[br * VLD + bc    ];
                blf[1] = *(const uint32_t*)&Vtl[br * VLD + bc + 8];
                mma16816(o[j], pah, bhf);
                mma16816(o[j], pah, blf);
                mma16816(o[j], pal, bhf);
            }
        }

        __syncthreads();
        if (ti + 2 < nt)
            attn_issue(St + st * STAGE_B, bh, qoff, (ti + 2) * 64, tid);
    }

    const float inv0 = 1.f / l0;
    const float inv1 = 1.f / l1;
    #pragma unroll
    for (int j = 0; j < 8; j++) {
        const int d = j * 8 + ((lane & 3) << 1);
        float2 w0 = make_float2(o[j][0] * inv0, o[j][1] * inv0);
        float2 w1 = make_float2(o[j][2] * inv1, o[j][3] * inv1);
        *(float2*)&out[(b * S_ + r0g) * E_ + h * D_ + d] = w0;
        *(float2*)&out[(b * S_ + r1g) * E_ + h * D_ + d] = w1;
    }
}

// ---------------------------------------------------------------------------
extern "C" void kernel_launch(void* const* d_in, const int* in_sizes, int n_in,
                              void* d_out, int out_size)
{
    const float* x   = (const float*)d_in[0];
    const float* Wq  = (const float*)d_in[1];
    const float* bq  = (const float*)d_in[2];
    const float* Wk  = (const float*)d_in[3];
    const float* bk  = (const float*)d_in[4];
    const float* Wv  = (const float*)d_in[5];
    const float* bv  = (const float*)d_in[6];
    const int*  lens = (const int*)d_in[7];
    float* out = (float*)d_out;

    // Projections: TF32 single-pass, reads X and W directly
    cudaFuncSetAttribute(qkv_mma,
                         cudaFuncAttributeMaxDynamicSharedMemorySize, QKV_SMEM);
    dim3 ggrid(E_ / TBN, M_ / TBM, 3);
    qkv_mma<<<ggrid, 256, QKV_SMEM>>>(x, Wq, bq, Wk, bk, Wv, bv);

    // Attention: tf32 QK^T + bf16 3-pass PV
    cudaFuncSetAttribute(attn_mma,
                         cudaFuncAttributeMaxDynamicSharedMemorySize, AT_SMEM_BYTES);
    dim3 agrid(S_ / 64, B_ * H_);
    attn_mma<<<agrid, 128, AT_SMEM_BYTES>>>(lens, out);
}